// round 9
// baseline (speedup 1.0000x reference)
#include <cuda_runtime.h>
#include <cuda_bf16.h>
#include <math.h>
#include <stdint.h>

// Problem constants
#define BB 4
#define NN 100
#define TT 20
#define HH 64
#define OO 128
#define MM 40000            // B*N*N edges
#define NE 8                // edges per group
#define NGROUPS (MM/NE)     // 5000
#define ESLOT 22            // [0]=left pad, [1..20]=t, [21]=right pad
#define XRP 180             // pair-row stride in uint2 units (==4 mod 16)
#define PS 36               // efa_p per-edge stride (conflict-free spatial B)
#define NTHREADS 256
#define NBLOCKS 444         // 3 CTAs per SM

// Scratch
__device__ float g_efa[MM * HH];   // 10.24 MB
__device__ float g_score[MM];
__device__ float g_attw[MM];
__device__ float g_A1[HH * 3];
__device__ float g_Bb[HH * 3];

// ---- helpers ---------------------------------------------------------------
__device__ __forceinline__ float tanha(float x) {
    float y;
    asm("tanh.approx.f32 %0, %1;" : "=f"(y) : "f"(x));
    return y;
}
// pack two f32 -> bf16x2 word; 'lo' lands in low 16 bits (first element)
__device__ __forceinline__ uint32_t pkbf2(float lo, float hi) {
    uint32_t r;
    asm("cvt.rn.bf16x2.f32 %0, %1, %2;" : "=r"(r) : "f"(hi), "f"(lo));
    return r;
}
__device__ __forceinline__ float bfu_lo(uint32_t w) {
    return __uint_as_float(w << 16);
}
__device__ __forceinline__ float bfu_hi(uint32_t w) {
    return __uint_as_float(w & 0xffff0000u);
}
__device__ __forceinline__ void mma_bf16(float d[4], uint4 a,
                                         uint32_t b0, uint32_t b1) {
    asm volatile(
        "mma.sync.aligned.m16n8k16.row.col.f32.bf16.bf16.f32 "
        "{%0,%1,%2,%3},{%4,%5,%6,%7},{%8,%9},{%0,%1,%2,%3};"
        : "+f"(d[0]), "+f"(d[1]), "+f"(d[2]), "+f"(d[3])
        : "r"(a.x), "r"(a.y), "r"(a.z), "r"(a.w), "r"(b0), "r"(b1));
}

// ---------------------------------------------------------------------------
// K0: fold conv1 weights against the rank-1 edge embedding
// ---------------------------------------------------------------------------
__global__ void k_prep(const float* __restrict__ w1,
                       const float* __restrict__ We,
                       const float* __restrict__ be) {
    int idx = threadIdx.x;
    if (idx < HH * 3) {
        int h = idx / 3, k = idx % 3;
        float a = 0.f, c = 0.f;
        for (int i = 0; i < HH; ++i) {
            float w = w1[(h * HH + i) * 3 + k];
            a += w * We[i];
            c += w * be[i];
        }
        g_A1[idx] = a;
        g_Bb[idx] = c;
    }
}

// ---------------------------------------------------------------------------
// K2: fused per-edge pipeline; pair-interleaved tile (LDS.64 gathers),
// 256 threads, 8 edges/group, 3 CTAs/SM.
// SMEM word offsets:
#define S_W2F   0           // 6144 : conv2 A-frags (bf16x2)
#define S_WT1F  6144        // 2048 : Wt1 A-frags (bf16x2, sigma-perm)
#define S_WS1F  8192        // 2048 : Ws1 A-frags (bf16x2, sigma-perm)
#define S_XS    10240       // 5760 : pair-interleaved tile, 16 rp x XRP uint2
#define S_ES    16000       // 160
#define S_ATT   16160       // 160
#define S_SPART 16320       // 704  : 4 htiles x 176 (indexed by column)
#define S_EFAP  17024       // 288  : 8 edges x PS, bf16x2 sigma-pairs
#define S_SS2   17312       // 32
#define S_TOTAL 17344       // words -> 69376 B per CTA
// ---------------------------------------------------------------------------
extern __shared__ float smem[];

__global__ void __launch_bounds__(NTHREADS, 3) k_edge(
    const float* __restrict__ ew,   const float* __restrict__ b1,
    const float* __restrict__ w2,   const float* __restrict__ b2,
    const float* __restrict__ Wt1,  const float* __restrict__ bt1,
    const float* __restrict__ Wt2,  const float* __restrict__ bt2,
    const float* __restrict__ Ws1,  const float* __restrict__ bs1,
    const float* __restrict__ Ws2,  const float* __restrict__ bs2)
{
    uint32_t* w2f   = (uint32_t*)(smem + S_W2F);
    uint32_t* wt1f  = (uint32_t*)(smem + S_WT1F);
    uint32_t* ws1f  = (uint32_t*)(smem + S_WS1F);
    uint32_t* xsu   = (uint32_t*)(smem + S_XS);   // 32-bit view
    uint2*    xs64  = (uint2*)(smem + S_XS);      // pair view
    float* e_s   = smem + S_ES;
    float* att_s = smem + S_ATT;
    float* spart = smem + S_SPART;
    uint32_t* efa_p = (uint32_t*)(smem + S_EFAP);
    float* ss2   = smem + S_SS2;

    const int tid  = threadIdx.x;
    const int w    = tid >> 5;
    const int lane = tid & 31;
    const int htile = w & 3;       // 16 h-rows each
    const int nhalf = w >> 2;      // 0..1, one 4-edge window (80 cols)
    const int gid  = lane >> 2;    // 0..7
    const int tig  = lane & 3;     // 0..3

    // ---- one-time init: conv2 bf16 A-frags ----------------------------------
    for (int f = tid; f < 4 * 12 * 32; f += NTHREADS) {
        int ht = f / 384, rem = f % 384, kb = rem / 32, ln = rem % 32;
        int r = ht * 16 + (ln >> 2);
        int k0 = (ln & 3) * 2;
        int kk = kb >> 2, ibase = (kb & 3) * 16;
        #pragma unroll
        for (int j = 0; j < 4; ++j) {
            int h  = r + (j & 1) * 8;
            int kl = k0 + (j >> 1) * 8;
            float v0 = w2[(h * 64 + ibase + kl) * 3 + kk];
            float v1 = w2[(h * 64 + ibase + kl + 1) * 3 + kk];
            w2f[f * 4 + j] = pkbf2(v0, v1);
        }
    }
    // Wt1 bf16 A-frags with sigma k-permutation (pair P -> h_in pair (s, s+8))
    for (int f = tid; f < 4 * 4 * 32; f += NTHREADS) {
        int ht = f / 128, rem = f % 128, kb = rem / 32, ln = rem % 32;
        int r = ht * 16 + (ln >> 2);
        int tg = ln & 3;
        #pragma unroll
        for (int j = 0; j < 4; ++j) {
            int P = kb * 8 + tg + (j >> 1) * 4;
            int hh = r + (j & 1) * 8;
            int s = (P >> 3) * 16 + (P & 7);
            wt1f[f * 4 + j] = pkbf2(Wt1[s * 64 + hh], Wt1[(s + 8) * 64 + hh]);
        }
    }
    // Ws1 bf16 A-frags, same sigma pairing
    for (int f = tid; f < 4 * 4 * 32; f += NTHREADS) {
        int ht = f / 128, rem = f % 128, kb = rem / 32, ln = rem % 32;
        int r = ht * 16 + (ln >> 2);
        int tg = ln & 3;
        #pragma unroll
        for (int j = 0; j < 4; ++j) {
            int P = kb * 8 + tg + (j >> 1) * 4;
            int hh = r + (j & 1) * 8;
            int s = (P >> 3) * 16 + (P & 7);
            ws1f[f * 4 + j] = pkbf2(Ws1[s * 64 + hh], Ws1[(s + 8) * 64 + hh]);
        }
    }
    // zero pad columns of the pair tile (both halves of each uint2)
    for (int f = tid; f < 16 * 2 * NE; f += NTHREADS) {
        int rp = f / (2 * NE), p = f % (2 * NE);
        int e = p >> 1, side = p & 1;
        xs64[rp * XRP + e * ESLOT + side * 21] = make_uint2(0u, 0u);
    }

    // ---- residue-perm column LUTs (conflict-free MMA gathers) ---------------
    int cq[10], dc0[10], dc1[10];
    {
        const int wb = nhalf * 4 * ESLOT;
        int n0 = 0, n1 = 0, n2 = 0;
        for (int e4 = 0; e4 < 4; ++e4)
            for (int t = 0; t < TT; ++t) {
                int col = wb + e4 * ESLOT + 1 + t;
                int r8 = col & 7;
                if (r8 == gid)            cq[n0++] = col;
                if (r8 == 2 * tig)        dc0[n1++] = col;
                if (r8 == 2 * tig + 1)    dc1[n2++] = col;
            }
    }
    const int r0 = htile * 16 + gid;   // D rows r0, r0+8
    const float b2_0 = b2[r0],  b2_1 = b2[r0 + 8];
    const float bt1_0 = bt1[r0], bt1_1 = bt1[r0 + 8];
    const float wt2_0 = Wt2[r0], wt2_1 = Wt2[r0 + 8];
    const float bt2v = bt2[0];
    const float bs2v = bs2[0];

    // x1-stage mapping: thread -> pair-row (channels 2prow, 2prow+1), one edge
    const int prow = tid >> 3;         // 0..31
    const int xe = tid & 7;            // edge 0..7
    const int xrp = ((prow >> 3) << 2) | (prow & 3);
    const int xhi = (prow >> 2) & 1;
    const int c0 = prow * 2, c1 = c0 + 1;
    float a1k0[3], a1k1[3];
    float s0c = 0.f, s1c = 0.f;
    #pragma unroll
    for (int k = 0; k < 3; ++k) {
        a1k0[k] = g_A1[c0 * 3 + k];  a1k1[k] = g_A1[c1 * 3 + k];
        s0c += g_Bb[c0 * 3 + k];     s1c += g_Bb[c1 * 3 + k];
    }
    const float c3_0 = b1[c0] + s0c;
    const float c3_1 = b1[c1] + s1c;
    const float ca_0 = c3_0 - g_Bb[c0 * 3 + 0];   // t = 0
    const float ca_1 = c3_1 - g_Bb[c1 * 3 + 0];
    const float cb_0 = c3_0 - g_Bb[c0 * 3 + 2];   // t = 19
    const float cb_1 = c3_1 - g_Bb[c1 * 3 + 2];

    // efa-stage mapping: warp covers 8 pair-rows x 4 edges
    const int fpr = (w & 3) * 8 + (lane & 7);     // pair-row 0..31
    const int fe  = (w >> 2) * 4 + (lane >> 3);   // edge 0..7
    const int frp = ((fpr >> 3) << 2) | (fpr & 3);
    const int fhi = (fpr >> 2) & 1;
    const int fh0 = (fpr >> 3) * 16 + (fpr & 7);
    const int fh1 = fh0 + 8;

    // prefetch first group's edge scalars
    float epref = 0.f;
    if (blockIdx.x < NGROUPS && tid < NE * TT)
        epref = ew[blockIdx.x * (NE * TT) + tid];

    for (int g = blockIdx.x; g < NGROUPS; g += gridDim.x) {
        const int m0 = g * NE;

        if (tid < NE * TT) e_s[tid] = epref;
        const int gn = g + gridDim.x;
        if (gn < NGROUPS && tid < NE * TT)
            epref = ew[gn * (NE * TT) + tid];
        __syncthreads();

        // ---- x1 = relu(folded conv1), packed bf16x2 by channel pair ----------
        {
            const float* ep = e_s + xe * TT;
            uint32_t* oa = xsu + (xrp * XRP + xe * ESLOT + 1) * 2 + xhi;
            #pragma unroll
            for (int t = 0; t < TT; ++t) {
                float x0, x1v;
                if (t == 0) {
                    x0 = ca_0 + a1k0[1] * ep[0] + a1k0[2] * ep[1];
                    x1v = ca_1 + a1k1[1] * ep[0] + a1k1[2] * ep[1];
                } else if (t == 19) {
                    x0 = cb_0 + a1k0[0] * ep[18] + a1k0[1] * ep[19];
                    x1v = cb_1 + a1k1[0] * ep[18] + a1k1[1] * ep[19];
                } else {
                    x0 = c3_0 + a1k0[0]*ep[t-1] + a1k0[1]*ep[t] + a1k0[2]*ep[t+1];
                    x1v = c3_1 + a1k1[0]*ep[t-1] + a1k1[1]*ep[t] + a1k1[2]*ep[t+1];
                }
                oa[t * 2] = pkbf2(fmaxf(x0, 0.f), fmaxf(x1v, 0.f));
            }
        }
        __syncthreads();

        // ---- conv2 via bf16 MMA: D[64 x 160], K = 192 (LDS.64 B-gathers) -----
        float d[10][4];
        #pragma unroll
        for (int q = 0; q < 10; ++q)
            #pragma unroll
            for (int j = 0; j < 4; ++j) d[q][j] = 0.f;

        #pragma unroll 1
        for (int kb = 0; kb < 12; ++kb) {
            const int fo = ((htile * 12 + kb) * 32 + lane) * 4;
            const uint4 A = *(const uint4*)(w2f + fo);
            const int rp = (kb & 3) * 4 + tig;
            const int koff = (kb >> 2) - 1;
            const uint2* bp = xs64 + rp * XRP + koff;
            #pragma unroll
            for (int q = 0; q < 10; ++q) {
                uint2 b = bp[cq[q]];
                mma_bf16(d[q], A, b.x, b.y);
            }
        }
        __syncthreads();  // all B reads done before overwriting the tile

        // ---- epilogue: x2 = relu(d+b2) packed (r0, r0+8) -> pair-row ----------
        {
            const int erp = htile * 4 + (gid & 3);
            const int ehi = (gid >> 2) & 1;
            uint32_t* op = xsu + erp * XRP * 2 + ehi;
            #pragma unroll
            for (int q = 0; q < 10; ++q) {
                op[dc0[q] * 2] = pkbf2(fmaxf(d[q][0] + b2_0, 0.f),
                                       fmaxf(d[q][2] + b2_1, 0.f));
                op[dc1[q] * 2] = pkbf2(fmaxf(d[q][1] + b2_0, 0.f),
                                       fmaxf(d[q][3] + b2_1, 0.f));
            }
        }
        __syncthreads();

        // ---- u_pre = Wt1^T @ x2 via bf16 MMA (LDS.64 B-gathers) ---------------
        float d2[10][4];
        #pragma unroll
        for (int q = 0; q < 10; ++q)
            #pragma unroll
            for (int j = 0; j < 4; ++j) d2[q][j] = 0.f;

        #pragma unroll 1
        for (int kb = 0; kb < 4; ++kb) {
            const int fo = ((htile * 4 + kb) * 32 + lane) * 4;
            const uint4 A = *(const uint4*)(wt1f + fo);
            const uint2* bp = xs64 + (kb * 4 + tig) * XRP;
            #pragma unroll
            for (int q = 0; q < 10; ++q) {
                uint2 b = bp[cq[q]];
                mma_bf16(d2[q], A, b.x, b.y);
            }
        }

        // ---- score partials (indexed by column) -------------------------------
        #pragma unroll
        for (int q = 0; q < 10; ++q) {
            float s0 = tanha(d2[q][0] + bt1_0) * wt2_0
                     + tanha(d2[q][2] + bt1_1) * wt2_1;
            float s1 = tanha(d2[q][1] + bt1_0) * wt2_0
                     + tanha(d2[q][3] + bt1_1) * wt2_1;
            #pragma unroll
            for (int off = 4; off < 32; off <<= 1) {
                s0 += __shfl_xor_sync(0xffffffffu, s0, off);
                s1 += __shfl_xor_sync(0xffffffffu, s1, off);
            }
            if (lane < 4) {
                spart[htile * 176 + dc0[q]] = s0;
                spart[htile * 176 + dc1[q]] = s1;
            }
        }
        __syncthreads();

        // ---- temporal softmax: warp w handles edge w --------------------------
        {
            float v = -1e30f;
            if (lane < TT) {
                int col = w * ESLOT + 1 + lane;
                v = spart[col] + spart[176 + col] + spart[352 + col]
                  + spart[528 + col] + bt2v;
            }
            float mx = v;
            #pragma unroll
            for (int off = 16; off; off >>= 1)
                mx = fmaxf(mx, __shfl_xor_sync(0xffffffffu, mx, off));
            float ev = (lane < TT) ? expf(v - mx) : 0.f;
            float sum = ev;
            #pragma unroll
            for (int off = 16; off; off >>= 1)
                sum += __shfl_xor_sync(0xffffffffu, sum, off);
            if (lane < TT) att_s[w * TT + lane] = ev / sum;
        }
        __syncthreads();

        // ---- efa: (pair-row, edge) per thread; pack sigma-pairs ---------------
        {
            const uint32_t* xr = xsu + (frp * XRP + fe * ESLOT + 1) * 2 + fhi;
            const float* at = att_s + fe * TT;
            float a0 = 0.f, a1 = 0.f;
            #pragma unroll
            for (int t = 0; t < TT; ++t) {
                uint32_t wd = xr[t * 2];
                float av = at[t];
                a0 += bfu_lo(wd) * av;
                a1 += bfu_hi(wd) * av;
            }
            efa_p[fe * PS + fpr] = pkbf2(a0, a1);   // P == fpr
            g_efa[(m0 + fe) * 64 + fh0] = a0;
            g_efa[(m0 + fe) * 64 + fh1] = a1;
        }
        __syncthreads();

        // ---- spatial score via bf16 MMA: D[64h x 8e], K = 64 ------------------
        if (w < 4) {
            const int ht2 = w;
            float d3[4] = {0.f, 0.f, 0.f, 0.f};
            #pragma unroll
            for (int kb = 0; kb < 4; ++kb) {
                const int fo = ((ht2 * 4 + kb) * 32 + lane) * 4;
                const uint4 A = *(const uint4*)(ws1f + fo);
                uint32_t b0 = efa_p[gid * PS + kb * 8 + tig];
                uint32_t b1 = efa_p[gid * PS + kb * 8 + tig + 4];
                mma_bf16(d3, A, b0, b1);
            }
            const int rr0 = ht2 * 16 + gid;
            float v0 = tanha(d3[0] + bs1[rr0]) * Ws2[rr0]
                     + tanha(d3[2] + bs1[rr0 + 8]) * Ws2[rr0 + 8];
            float v1 = tanha(d3[1] + bs1[rr0]) * Ws2[rr0]
                     + tanha(d3[3] + bs1[rr0 + 8]) * Ws2[rr0 + 8];
            #pragma unroll
            for (int off = 4; off < 32; off <<= 1) {
                v0 += __shfl_xor_sync(0xffffffffu, v0, off);
                v1 += __shfl_xor_sync(0xffffffffu, v1, off);
            }
            if (lane < 4) {
                int e0 = lane * 2;
                ss2[ht2 * 8 + e0]     = v0;
                ss2[ht2 * 8 + e0 + 1] = v1;
            }
        }
        __syncthreads();
        if (tid < NE)
            g_score[m0 + tid] = ss2[tid] + ss2[8 + tid] + ss2[16 + tid]
                              + ss2[24 + tid] + bs2v;
    }
}

// ---------------------------------------------------------------------------
// K3: per-batch spatial softmax over N*N = 10000 scores
// ---------------------------------------------------------------------------
__global__ void __launch_bounds__(1024) k_spatial() {
    __shared__ float red[1024];
    __shared__ float mx_s, z_s;
    int b = blockIdx.x, tid = threadIdx.x;
    const float* sc = g_score + b * (NN * NN);

    float mx = -1e30f;
    for (int i = tid; i < NN * NN; i += 1024) mx = fmaxf(mx, sc[i]);
    red[tid] = mx;
    __syncthreads();
    for (int s = 512; s; s >>= 1) {
        if (tid < s) red[tid] = fmaxf(red[tid], red[tid + s]);
        __syncthreads();
    }
    if (tid == 0) mx_s = red[0];
    __syncthreads();
    float m = mx_s, z = 0.f;
    for (int i = tid; i < NN * NN; i += 1024) z += expf(sc[i] - m);
    red[tid] = z;
    __syncthreads();
    for (int s = 512; s; s >>= 1) {
        if (tid < s) red[tid] += red[tid + s];
        __syncthreads();
    }
    if (tid == 0) z_s = red[0];
    __syncthreads();
    float inv = 1.f / z_s;
    for (int i = tid; i < NN * NN; i += 1024)
        g_attw[b * (NN * NN) + i] = expf(sc[i] - m) * inv;
}

// ---------------------------------------------------------------------------
// K4: node aggregation + 3-layer MLP. One block per (b,i) node.
// ---------------------------------------------------------------------------
__global__ void __launch_bounds__(256) k_node(
    const float* __restrict__ Wg1, const float* __restrict__ bg1,
    const float* __restrict__ Wg2, const float* __restrict__ bg2,
    const float* __restrict__ Wout, const float* __restrict__ bout,
    float* __restrict__ out)
{
    __shared__ float nsm[256], g1s[64], g2s[64];
    const int bi = blockIdx.x;
    const int tid = threadIdx.x;
    const int h = tid & 63, quarter = tid >> 6;

    const float* efa = g_efa + (size_t)bi * NN * HH;
    const float* aw  = g_attw + bi * NN;
    float a = 0.f;
    #pragma unroll 5
    for (int j = quarter * 25; j < quarter * 25 + 25; ++j)
        a += efa[j * 64 + h] * aw[j];
    nsm[tid] = a;
    __syncthreads();
    if (tid < 64) {
        float s = nsm[tid] + nsm[tid + 64] + nsm[tid + 128] + nsm[tid + 192];
        nsm[tid] = s;
    }
    __syncthreads();
    if (tid < 64) {
        float acc = bg1[tid];
        for (int i = 0; i < 64; ++i) acc += nsm[i] * Wg1[i * 64 + tid];
        g1s[tid] = fmaxf(acc, 0.f);
    }
    __syncthreads();
    if (tid < 64) {
        float acc = bg2[tid];
        for (int i = 0; i < 64; ++i) acc += g1s[i] * Wg2[i * 64 + tid];
        g2s[tid] = fmaxf(acc, 0.f);
    }
    __syncthreads();
    if (tid < OO) {
        float acc = bout[tid];
        for (int i = 0; i < 64; ++i) acc += g2s[i] * Wout[i * OO + tid];
        out[bi * OO + tid] = fmaxf(acc, 0.f);
    }
}

// ---------------------------------------------------------------------------
extern "C" void kernel_launch(void* const* d_in, const int* in_sizes, int n_in,
                              void* d_out, int out_size) {
    const float* ew   = (const float*)d_in[0];
    const float* We   = (const float*)d_in[1];
    const float* be   = (const float*)d_in[2];
    const float* w1   = (const float*)d_in[3];
    const float* b1   = (const float*)d_in[4];
    const float* w2   = (const float*)d_in[5];
    const float* b2   = (const float*)d_in[6];
    const float* Wt1  = (const float*)d_in[7];
    const float* bt1  = (const float*)d_in[8];
    const float* Wt2  = (const float*)d_in[9];
    const float* bt2  = (const float*)d_in[10];
    const float* Ws1  = (const float*)d_in[11];
    const float* bs1  = (const float*)d_in[12];
    const float* Ws2  = (const float*)d_in[13];
    const float* bs2  = (const float*)d_in[14];
    const float* Wg1  = (const float*)d_in[15];
    const float* bg1  = (const float*)d_in[16];
    const float* Wg2  = (const float*)d_in[17];
    const float* bg2  = (const float*)d_in[18];
    const float* Wout = (const float*)d_in[19];
    const float* bout = (const float*)d_in[20];
    float* out = (float*)d_out;

    const int smem_bytes = S_TOTAL * 4;  // 69376 B per CTA
    cudaFuncSetAttribute(k_edge, cudaFuncAttributeMaxDynamicSharedMemorySize,
                         smem_bytes);

    k_prep<<<1, 256>>>(w1, We, be);
    k_edge<<<NBLOCKS, NTHREADS, smem_bytes>>>(ew, b1, w2, b2, Wt1, bt1,
                                              Wt2, bt2, Ws1, bs1, Ws2, bs2);
    k_spatial<<<BB, 1024>>>();
    k_node<<<BB * NN, 256>>>(Wg1, bg1, Wg2, bg2, Wout, bout, out);
}

// round 10
// speedup vs baseline: 1.1386x; 1.1386x over previous
#include <cuda_runtime.h>
#include <cuda_bf16.h>
#include <math.h>
#include <stdint.h>

// Problem constants
#define BB 4
#define NN 100
#define TT 20
#define HH 64
#define OO 128
#define MM 40000            // B*N*N edges
#define NE 8                // edges per group
#define NGROUPS (MM/NE)     // 5000
#define ESLOT 22            // [0]=left pad, [1..20]=t, [21]=right pad
#define XRP 180             // pair-row stride in uint2 units (==4 mod 16)
#define PS 36               // efa_p per-edge stride (conflict-free spatial B)
#define NTHREADS 256
#define NBLOCKS 296         // 2 CTAs per SM

// Scratch
__device__ float g_efa[MM * HH];   // 10.24 MB
__device__ float g_score[MM];
__device__ float g_attw[MM];
__device__ float g_A1[HH * 3];
__device__ float g_Bb[HH * 3];

// ---- helpers ---------------------------------------------------------------
__device__ __forceinline__ float tanha(float x) {
    float y;
    asm("tanh.approx.f32 %0, %1;" : "=f"(y) : "f"(x));
    return y;
}
// pack two f32 -> bf16x2 word; 'lo' lands in low 16 bits (first element)
__device__ __forceinline__ uint32_t pkbf2(float lo, float hi) {
    uint32_t r;
    asm("cvt.rn.bf16x2.f32 %0, %1, %2;" : "=r"(r) : "f"(hi), "f"(lo));
    return r;
}
__device__ __forceinline__ float bfu_lo(uint32_t w) {
    return __uint_as_float(w << 16);
}
__device__ __forceinline__ float bfu_hi(uint32_t w) {
    return __uint_as_float(w & 0xffff0000u);
}
__device__ __forceinline__ void mma_bf16(float d[4], uint4 a,
                                         uint32_t b0, uint32_t b1) {
    asm volatile(
        "mma.sync.aligned.m16n8k16.row.col.f32.bf16.bf16.f32 "
        "{%0,%1,%2,%3},{%4,%5,%6,%7},{%8,%9},{%0,%1,%2,%3};"
        : "+f"(d[0]), "+f"(d[1]), "+f"(d[2]), "+f"(d[3])
        : "r"(a.x), "r"(a.y), "r"(a.z), "r"(a.w), "r"(b0), "r"(b1));
}

// ---------------------------------------------------------------------------
// K0: fold conv1 weights against the rank-1 edge embedding
// ---------------------------------------------------------------------------
__global__ void k_prep(const float* __restrict__ w1,
                       const float* __restrict__ We,
                       const float* __restrict__ be) {
    int idx = threadIdx.x;
    if (idx < HH * 3) {
        int h = idx / 3, k = idx % 3;
        float a = 0.f, c = 0.f;
        for (int i = 0; i < HH; ++i) {
            float w = w1[(h * HH + i) * 3 + k];
            a += w * We[i];
            c += w * be[i];
        }
        g_A1[idx] = a;
        g_Bb[idx] = c;
    }
}

// ---------------------------------------------------------------------------
// K2: fused per-edge pipeline; pair-interleaved tile (LDS.64 gathers),
// 256 threads, 8 edges/group, 2 CTAs/SM (occupancy-2: no reg cap spills).
// SMEM word offsets:
#define S_W2F   0           // 6144 : conv2 A-frags (bf16x2)
#define S_WT1F  6144        // 2048 : Wt1 A-frags (bf16x2, sigma-perm)
#define S_WS1F  8192        // 2048 : Ws1 A-frags (bf16x2, sigma-perm)
#define S_XS    10240       // 5760 : pair-interleaved tile, 16 rp x XRP uint2
#define S_ES    16000       // 160
#define S_ATT   16160       // 160
#define S_SPART 16320       // 704  : 4 htiles x 176 (indexed by column)
#define S_EFAP  17024       // 288  : 8 edges x PS, bf16x2 sigma-pairs
#define S_SS2   17312       // 32
#define S_TOTAL 17344       // words -> 69376 B per CTA
// ---------------------------------------------------------------------------
extern __shared__ float smem[];

__global__ void __launch_bounds__(NTHREADS, 2) k_edge(
    const float* __restrict__ ew,   const float* __restrict__ b1,
    const float* __restrict__ w2,   const float* __restrict__ b2,
    const float* __restrict__ Wt1,  const float* __restrict__ bt1,
    const float* __restrict__ Wt2,  const float* __restrict__ bt2,
    const float* __restrict__ Ws1,  const float* __restrict__ bs1,
    const float* __restrict__ Ws2,  const float* __restrict__ bs2)
{
    uint32_t* w2f   = (uint32_t*)(smem + S_W2F);
    uint32_t* wt1f  = (uint32_t*)(smem + S_WT1F);
    uint32_t* ws1f  = (uint32_t*)(smem + S_WS1F);
    uint32_t* xsu   = (uint32_t*)(smem + S_XS);   // 32-bit view
    uint2*    xs64  = (uint2*)(smem + S_XS);      // pair view
    float* e_s   = smem + S_ES;
    float* att_s = smem + S_ATT;
    float* spart = smem + S_SPART;
    uint32_t* efa_p = (uint32_t*)(smem + S_EFAP);
    float* ss2   = smem + S_SS2;

    const int tid  = threadIdx.x;
    const int w    = tid >> 5;
    const int lane = tid & 31;
    const int htile = w & 3;       // 16 h-rows each
    const int nhalf = w >> 2;      // 0..1, one 4-edge window (80 cols)
    const int gid  = lane >> 2;    // 0..7
    const int tig  = lane & 3;     // 0..3

    // ---- one-time init: conv2 bf16 A-frags ----------------------------------
    for (int f = tid; f < 4 * 12 * 32; f += NTHREADS) {
        int ht = f / 384, rem = f % 384, kb = rem / 32, ln = rem % 32;
        int r = ht * 16 + (ln >> 2);
        int k0 = (ln & 3) * 2;
        int kk = kb >> 2, ibase = (kb & 3) * 16;
        #pragma unroll
        for (int j = 0; j < 4; ++j) {
            int h  = r + (j & 1) * 8;
            int kl = k0 + (j >> 1) * 8;
            float v0 = w2[(h * 64 + ibase + kl) * 3 + kk];
            float v1 = w2[(h * 64 + ibase + kl + 1) * 3 + kk];
            w2f[f * 4 + j] = pkbf2(v0, v1);
        }
    }
    // Wt1 bf16 A-frags with sigma k-permutation (pair P -> h_in pair (s, s+8))
    for (int f = tid; f < 4 * 4 * 32; f += NTHREADS) {
        int ht = f / 128, rem = f % 128, kb = rem / 32, ln = rem % 32;
        int r = ht * 16 + (ln >> 2);
        int tg = ln & 3;
        #pragma unroll
        for (int j = 0; j < 4; ++j) {
            int P = kb * 8 + tg + (j >> 1) * 4;
            int hh = r + (j & 1) * 8;
            int s = (P >> 3) * 16 + (P & 7);
            wt1f[f * 4 + j] = pkbf2(Wt1[s * 64 + hh], Wt1[(s + 8) * 64 + hh]);
        }
    }
    // Ws1 bf16 A-frags, same sigma pairing
    for (int f = tid; f < 4 * 4 * 32; f += NTHREADS) {
        int ht = f / 128, rem = f % 128, kb = rem / 32, ln = rem % 32;
        int r = ht * 16 + (ln >> 2);
        int tg = ln & 3;
        #pragma unroll
        for (int j = 0; j < 4; ++j) {
            int P = kb * 8 + tg + (j >> 1) * 4;
            int hh = r + (j & 1) * 8;
            int s = (P >> 3) * 16 + (P & 7);
            ws1f[f * 4 + j] = pkbf2(Ws1[s * 64 + hh], Ws1[(s + 8) * 64 + hh]);
        }
    }
    // zero pad columns of the pair tile (both halves of each uint2)
    for (int f = tid; f < 16 * 2 * NE; f += NTHREADS) {
        int rp = f / (2 * NE), p = f % (2 * NE);
        int e = p >> 1, side = p & 1;
        xs64[rp * XRP + e * ESLOT + side * 21] = make_uint2(0u, 0u);
    }

    // ---- residue-perm column LUTs (conflict-free MMA gathers) ---------------
    int cq[10], dc0[10], dc1[10];
    {
        const int wb = nhalf * 4 * ESLOT;
        int n0 = 0, n1 = 0, n2 = 0;
        for (int e4 = 0; e4 < 4; ++e4)
            for (int t = 0; t < TT; ++t) {
                int col = wb + e4 * ESLOT + 1 + t;
                int r8 = col & 7;
                if (r8 == gid)            cq[n0++] = col;
                if (r8 == 2 * tig)        dc0[n1++] = col;
                if (r8 == 2 * tig + 1)    dc1[n2++] = col;
            }
    }
    const int r0 = htile * 16 + gid;   // D rows r0, r0+8
    const float b2_0 = b2[r0],  b2_1 = b2[r0 + 8];
    const float bt1_0 = bt1[r0], bt1_1 = bt1[r0 + 8];
    const float wt2_0 = Wt2[r0], wt2_1 = Wt2[r0 + 8];
    const float bt2v = bt2[0];
    const float bs2v = bs2[0];

    // x1-stage mapping: thread -> pair-row (channels 2prow, 2prow+1), one edge
    const int prow = tid >> 3;         // 0..31
    const int xe = tid & 7;            // edge 0..7
    const int xrp = ((prow >> 3) << 2) | (prow & 3);
    const int xhi = (prow >> 2) & 1;
    const int c0 = prow * 2, c1 = c0 + 1;
    float a1k0[3], a1k1[3];
    float s0c = 0.f, s1c = 0.f;
    #pragma unroll
    for (int k = 0; k < 3; ++k) {
        a1k0[k] = g_A1[c0 * 3 + k];  a1k1[k] = g_A1[c1 * 3 + k];
        s0c += g_Bb[c0 * 3 + k];     s1c += g_Bb[c1 * 3 + k];
    }
    const float c3_0 = b1[c0] + s0c;
    const float c3_1 = b1[c1] + s1c;
    const float ca_0 = c3_0 - g_Bb[c0 * 3 + 0];   // t = 0
    const float ca_1 = c3_1 - g_Bb[c1 * 3 + 0];
    const float cb_0 = c3_0 - g_Bb[c0 * 3 + 2];   // t = 19
    const float cb_1 = c3_1 - g_Bb[c1 * 3 + 2];

    // efa-stage mapping: warp covers 8 pair-rows x 4 edges
    const int fpr = (w & 3) * 8 + (lane & 7);     // pair-row 0..31
    const int fe  = (w >> 2) * 4 + (lane >> 3);   // edge 0..7
    const int frp = ((fpr >> 3) << 2) | (fpr & 3);
    const int fhi = (fpr >> 2) & 1;
    const int fh0 = (fpr >> 3) * 16 + (fpr & 7);
    const int fh1 = fh0 + 8;

    // prefetch first group's edge scalars
    float epref = 0.f;
    if (blockIdx.x < NGROUPS && tid < NE * TT)
        epref = ew[blockIdx.x * (NE * TT) + tid];

    for (int g = blockIdx.x; g < NGROUPS; g += gridDim.x) {
        const int m0 = g * NE;

        if (tid < NE * TT) e_s[tid] = epref;
        const int gn = g + gridDim.x;
        if (gn < NGROUPS && tid < NE * TT)
            epref = ew[gn * (NE * TT) + tid];
        __syncthreads();

        // ---- x1 = relu(folded conv1), packed bf16x2 by channel pair ----------
        {
            const float* ep = e_s + xe * TT;
            uint32_t* oa = xsu + (xrp * XRP + xe * ESLOT + 1) * 2 + xhi;
            #pragma unroll
            for (int t = 0; t < TT; ++t) {
                float x0, x1v;
                if (t == 0) {
                    x0 = ca_0 + a1k0[1] * ep[0] + a1k0[2] * ep[1];
                    x1v = ca_1 + a1k1[1] * ep[0] + a1k1[2] * ep[1];
                } else if (t == 19) {
                    x0 = cb_0 + a1k0[0] * ep[18] + a1k0[1] * ep[19];
                    x1v = cb_1 + a1k1[0] * ep[18] + a1k1[1] * ep[19];
                } else {
                    x0 = c3_0 + a1k0[0]*ep[t-1] + a1k0[1]*ep[t] + a1k0[2]*ep[t+1];
                    x1v = c3_1 + a1k1[0]*ep[t-1] + a1k1[1]*ep[t] + a1k1[2]*ep[t+1];
                }
                oa[t * 2] = pkbf2(fmaxf(x0, 0.f), fmaxf(x1v, 0.f));
            }
        }
        __syncthreads();

        // ---- conv2 via bf16 MMA: D[64 x 160], K = 192 (LDS.64 B-gathers) -----
        float d[10][4];
        #pragma unroll
        for (int q = 0; q < 10; ++q)
            #pragma unroll
            for (int j = 0; j < 4; ++j) d[q][j] = 0.f;

        #pragma unroll 1
        for (int kb = 0; kb < 12; ++kb) {
            const int fo = ((htile * 12 + kb) * 32 + lane) * 4;
            const uint4 A = *(const uint4*)(w2f + fo);
            const int rp = (kb & 3) * 4 + tig;
            const int koff = (kb >> 2) - 1;
            const uint2* bp = xs64 + rp * XRP + koff;
            #pragma unroll
            for (int q = 0; q < 10; ++q) {
                uint2 b = bp[cq[q]];
                mma_bf16(d[q], A, b.x, b.y);
            }
        }
        __syncthreads();  // all B reads done before overwriting the tile

        // ---- epilogue: x2 = relu(d+b2) packed (r0, r0+8) -> pair-row ----------
        {
            const int erp = htile * 4 + (gid & 3);
            const int ehi = (gid >> 2) & 1;
            uint32_t* op = xsu + erp * XRP * 2 + ehi;
            #pragma unroll
            for (int q = 0; q < 10; ++q) {
                op[dc0[q] * 2] = pkbf2(fmaxf(d[q][0] + b2_0, 0.f),
                                       fmaxf(d[q][2] + b2_1, 0.f));
                op[dc1[q] * 2] = pkbf2(fmaxf(d[q][1] + b2_0, 0.f),
                                       fmaxf(d[q][3] + b2_1, 0.f));
            }
        }
        __syncthreads();

        // ---- u_pre = Wt1^T @ x2 via bf16 MMA (LDS.64 B-gathers) ---------------
        float d2[10][4];
        #pragma unroll
        for (int q = 0; q < 10; ++q)
            #pragma unroll
            for (int j = 0; j < 4; ++j) d2[q][j] = 0.f;

        #pragma unroll 1
        for (int kb = 0; kb < 4; ++kb) {
            const int fo = ((htile * 4 + kb) * 32 + lane) * 4;
            const uint4 A = *(const uint4*)(wt1f + fo);
            const uint2* bp = xs64 + (kb * 4 + tig) * XRP;
            #pragma unroll
            for (int q = 0; q < 10; ++q) {
                uint2 b = bp[cq[q]];
                mma_bf16(d2[q], A, b.x, b.y);
            }
        }

        // ---- score partials (indexed by column) -------------------------------
        #pragma unroll
        for (int q = 0; q < 10; ++q) {
            float s0 = tanha(d2[q][0] + bt1_0) * wt2_0
                     + tanha(d2[q][2] + bt1_1) * wt2_1;
            float s1 = tanha(d2[q][1] + bt1_0) * wt2_0
                     + tanha(d2[q][3] + bt1_1) * wt2_1;
            #pragma unroll
            for (int off = 4; off < 32; off <<= 1) {
                s0 += __shfl_xor_sync(0xffffffffu, s0, off);
                s1 += __shfl_xor_sync(0xffffffffu, s1, off);
            }
            if (lane < 4) {
                spart[htile * 176 + dc0[q]] = s0;
                spart[htile * 176 + dc1[q]] = s1;
            }
        }
        __syncthreads();

        // ---- temporal softmax: warp w handles edge w --------------------------
        {
            float v = -1e30f;
            if (lane < TT) {
                int col = w * ESLOT + 1 + lane;
                v = spart[col] + spart[176 + col] + spart[352 + col]
                  + spart[528 + col] + bt2v;
            }
            float mx = v;
            #pragma unroll
            for (int off = 16; off; off >>= 1)
                mx = fmaxf(mx, __shfl_xor_sync(0xffffffffu, mx, off));
            float ev = (lane < TT) ? expf(v - mx) : 0.f;
            float sum = ev;
            #pragma unroll
            for (int off = 16; off; off >>= 1)
                sum += __shfl_xor_sync(0xffffffffu, sum, off);
            if (lane < TT) att_s[w * TT + lane] = ev / sum;
        }
        __syncthreads();

        // ---- efa: (pair-row, edge) per thread; pack sigma-pairs ---------------
        {
            const uint32_t* xr = xsu + (frp * XRP + fe * ESLOT + 1) * 2 + fhi;
            const float* at = att_s + fe * TT;
            float a0 = 0.f, a1 = 0.f;
            #pragma unroll
            for (int t = 0; t < TT; ++t) {
                uint32_t wd = xr[t * 2];
                float av = at[t];
                a0 += bfu_lo(wd) * av;
                a1 += bfu_hi(wd) * av;
            }
            efa_p[fe * PS + fpr] = pkbf2(a0, a1);   // P == fpr
            g_efa[(m0 + fe) * 64 + fh0] = a0;
            g_efa[(m0 + fe) * 64 + fh1] = a1;
        }
        __syncthreads();

        // ---- spatial score via bf16 MMA: D[64h x 8e], K = 64 ------------------
        if (w < 4) {
            const int ht2 = w;
            float d3[4] = {0.f, 0.f, 0.f, 0.f};
            #pragma unroll
            for (int kb = 0; kb < 4; ++kb) {
                const int fo = ((ht2 * 4 + kb) * 32 + lane) * 4;
                const uint4 A = *(const uint4*)(ws1f + fo);
                uint32_t b0 = efa_p[gid * PS + kb * 8 + tig];
                uint32_t b1 = efa_p[gid * PS + kb * 8 + tig + 4];
                mma_bf16(d3, A, b0, b1);
            }
            const int rr0 = ht2 * 16 + gid;
            float v0 = tanha(d3[0] + bs1[rr0]) * Ws2[rr0]
                     + tanha(d3[2] + bs1[rr0 + 8]) * Ws2[rr0 + 8];
            float v1 = tanha(d3[1] + bs1[rr0]) * Ws2[rr0]
                     + tanha(d3[3] + bs1[rr0 + 8]) * Ws2[rr0 + 8];
            #pragma unroll
            for (int off = 4; off < 32; off <<= 1) {
                v0 += __shfl_xor_sync(0xffffffffu, v0, off);
                v1 += __shfl_xor_sync(0xffffffffu, v1, off);
            }
            if (lane < 4) {
                int e0 = lane * 2;
                ss2[ht2 * 8 + e0]     = v0;
                ss2[ht2 * 8 + e0 + 1] = v1;
            }
        }
        __syncthreads();
        if (tid < NE)
            g_score[m0 + tid] = ss2[tid] + ss2[8 + tid] + ss2[16 + tid]
                              + ss2[24 + tid] + bs2v;
    }
}

// ---------------------------------------------------------------------------
// K3: per-batch spatial softmax over N*N = 10000 scores
// ---------------------------------------------------------------------------
__global__ void __launch_bounds__(1024) k_spatial() {
    __shared__ float red[1024];
    __shared__ float mx_s, z_s;
    int b = blockIdx.x, tid = threadIdx.x;
    const float* sc = g_score + b * (NN * NN);

    float mx = -1e30f;
    for (int i = tid; i < NN * NN; i += 1024) mx = fmaxf(mx, sc[i]);
    red[tid] = mx;
    __syncthreads();
    for (int s = 512; s; s >>= 1) {
        if (tid < s) red[tid] = fmaxf(red[tid], red[tid + s]);
        __syncthreads();
    }
    if (tid == 0) mx_s = red[0];
    __syncthreads();
    float m = mx_s, z = 0.f;
    for (int i = tid; i < NN * NN; i += 1024) z += expf(sc[i] - m);
    red[tid] = z;
    __syncthreads();
    for (int s = 512; s; s >>= 1) {
        if (tid < s) red[tid] += red[tid + s];
        __syncthreads();
    }
    if (tid == 0) z_s = red[0];
    __syncthreads();
    float inv = 1.f / z_s;
    for (int i = tid; i < NN * NN; i += 1024)
        g_attw[b * (NN * NN) + i] = expf(sc[i] - m) * inv;
}

// ---------------------------------------------------------------------------
// K4: node aggregation + 3-layer MLP. One block per (b,i) node.
// ---------------------------------------------------------------------------
__global__ void __launch_bounds__(256) k_node(
    const float* __restrict__ Wg1, const float* __restrict__ bg1,
    const float* __restrict__ Wg2, const float* __restrict__ bg2,
    const float* __restrict__ Wout, const float* __restrict__ bout,
    float* __restrict__ out)
{
    __shared__ float nsm[256], g1s[64], g2s[64];
    const int bi = blockIdx.x;
    const int tid = threadIdx.x;
    const int h = tid & 63, quarter = tid >> 6;

    const float* efa = g_efa + (size_t)bi * NN * HH;
    const float* aw  = g_attw + bi * NN;
    float a = 0.f;
    #pragma unroll 5
    for (int j = quarter * 25; j < quarter * 25 + 25; ++j)
        a += efa[j * 64 + h] * aw[j];
    nsm[tid] = a;
    __syncthreads();
    if (tid < 64) {
        float s = nsm[tid] + nsm[tid + 64] + nsm[tid + 128] + nsm[tid + 192];
        nsm[tid] = s;
    }
    __syncthreads();
    if (tid < 64) {
        float acc = bg1[tid];
        for (int i = 0; i < 64; ++i) acc += nsm[i] * Wg1[i * 64 + tid];
        g1s[tid] = fmaxf(acc, 0.f);
    }
    __syncthreads();
    if (tid < 64) {
        float acc = bg2[tid];
        for (int i = 0; i < 64; ++i) acc += g1s[i] * Wg2[i * 64 + tid];
        g2s[tid] = fmaxf(acc, 0.f);
    }
    __syncthreads();
    if (tid < OO) {
        float acc = bout[tid];
        for (int i = 0; i < 64; ++i) acc += g2s[i] * Wout[i * OO + tid];
        out[bi * OO + tid] = fmaxf(acc, 0.f);
    }
}

// ---------------------------------------------------------------------------
extern "C" void kernel_launch(void* const* d_in, const int* in_sizes, int n_in,
                              void* d_out, int out_size) {
    const float* ew   = (const float*)d_in[0];
    const float* We   = (const float*)d_in[1];
    const float* be   = (const float*)d_in[2];
    const float* w1   = (const float*)d_in[3];
    const float* b1   = (const float*)d_in[4];
    const float* w2   = (const float*)d_in[5];
    const float* b2   = (const float*)d_in[6];
    const float* Wt1  = (const float*)d_in[7];
    const float* bt1  = (const float*)d_in[8];
    const float* Wt2  = (const float*)d_in[9];
    const float* bt2  = (const float*)d_in[10];
    const float* Ws1  = (const float*)d_in[11];
    const float* bs1  = (const float*)d_in[12];
    const float* Ws2  = (const float*)d_in[13];
    const float* bs2  = (const float*)d_in[14];
    const float* Wg1  = (const float*)d_in[15];
    const float* bg1  = (const float*)d_in[16];
    const float* Wg2  = (const float*)d_in[17];
    const float* bg2  = (const float*)d_in[18];
    const float* Wout = (const float*)d_in[19];
    const float* bout = (const float*)d_in[20];
    float* out = (float*)d_out;

    const int smem_bytes = S_TOTAL * 4;  // 69376 B per CTA
    cudaFuncSetAttribute(k_edge, cudaFuncAttributeMaxDynamicSharedMemorySize,
                         smem_bytes);

    k_prep<<<1, 256>>>(w1, We, be);
    k_edge<<<NBLOCKS, NTHREADS, smem_bytes>>>(ew, b1, w2, b2, Wt1, bt1,
                                              Wt2, bt2, Ws1, bs1, Ws2, bs2);
    k_spatial<<<BB, 1024>>>();
    k_node<<<BB * NN, 256>>>(Wg1, bg1, Wg2, bg2, Wout, bout, out);
}